// round 10
// baseline (speedup 1.0000x reference)
#include <cuda_runtime.h>
#include <cuda_bf16.h>

// AttentionGate fused kernel, round 10: occupancy + MLP (latency-bound fix).
//
// psi = sigmoid(Wpsi . relu(Wg@g + Wx@x));  out = x * psi
// B=2, CF=CG=64, CI=32, DHW=64^3=262144.
//
// Round 9 was LATENCY bound: issue 20.8%, occ 22.2% (128 regs -> 16 warps/SM),
// no unit above 59%. This round shrinks the per-thread tile to 4 u64 streams
// (acc = 32 regs, launch_bounds(256,3) -> 24 warps/SM) and fuses the g/x
// loops so each iteration front-batches 4 independent LDG.128 (2 from g,
// 2 from x) -> 2x per-warp MLP. Chip-level instruction totals unchanged
// (2x warps, half per-warp work): FFMA2 floor ~63us, LDS/LSU below that.

#define HALFV  131072           // u64 (f32x2) elements per channel-plane
#define PLANE2 65536            // ulonglong2 elements per channel-plane

typedef unsigned long long u64;

__device__ __forceinline__ u64 ffma2(u64 a, u64 b, u64 c) {
    u64 d;
    asm("fma.rn.f32x2 %0, %1, %2, %3;" : "=l"(d) : "l"(a), "l"(b), "l"(c));
    return d;
}
__device__ __forceinline__ u64 fmul2(u64 a, u64 b) {
    u64 d;
    asm("mul.rn.f32x2 %0, %1, %2;" : "=l"(d) : "l"(a), "l"(b));
    return d;
}
__device__ __forceinline__ u64 pack2(float lo, float hi) {
    u64 r;
    asm("mov.b64 %0, {%1, %2};" : "=l"(r) : "f"(lo), "f"(hi));
    return r;
}
__device__ __forceinline__ float2 unpack2(u64 v) {
    float2 r;
    asm("mov.b64 {%0, %1}, %2;" : "=f"(r.x), "=f"(r.y) : "l"(v));
    return r;
}

__global__ __launch_bounds__(256, 3)
void attn_gate_kernel(const float* __restrict__ x,
                      const float* __restrict__ g,
                      const float* __restrict__ Wg,
                      const float* __restrict__ Wx,
                      const float* __restrict__ Wpsi,
                      float* __restrict__ out)
{
    // Wc[k] row (32 u64): channel o = 4q + 2c + lh at u64 index 2*(8c+q)+lh;
    // the warp's LDS.128 #c covers chunks [8c..8c+7] = 128B contiguous over
    // the 8 q-lanes -> conflict-free.
    __shared__ u64   Wc[128][32];      // 32 KiB
    __shared__ float wpsi_s[32];

    for (int idx = threadIdx.x; idx < 128 * 32; idx += 256) {
        int k = idx >> 5;
        int o = idx & 31;
        int qq = o >> 2, cc = (o >> 1) & 1, lh = o & 1;
        float w = (k < 64) ? Wg[o * 64 + k] : Wx[o * 64 + (k - 64)];
        Wc[k][2 * (8 * cc + qq) + lh] = pack2(w, w);
    }
    if (threadIdx.x < 32) wpsi_s[threadIdx.x] = Wpsi[threadIdx.x];
    __syncthreads();

    int t    = blockIdx.x * 256 + threadIdx.x;
    int lane = t & 31;
    int wid  = t >> 5;            // 0..16383
    int gl   = lane >> 3;         // 0..3 spatial subgroup
    int q    = lane & 7;          // CI eighth: channels [4q, 4q+4)

    int pbase = wid * 16;                              // warp's first pair
    int b     = pbase >> 17;                           // batch
    int sp2   = ((pbase & (HALFV - 1)) >> 1) + gl;     // ulonglong2 index

    // Thread's 2 loads at u2 offsets {0, 4}: warp covers 8 contiguous u2
    // = 128B per load instruction.
    size_t cbase = (size_t)(b * 64) * PLANE2 + sp2;
    const ulonglong2* g2 = (const ulonglong2*)g + cbase;
    const ulonglong2* x2 = (const ulonglong2*)x + cbase;

    u64 acc[4][4];                // [channel][stream u64]
    #pragma unroll
    for (int i = 0; i < 4; i++)
        #pragma unroll
        for (int s = 0; s < 4; s++) acc[i][s] = 0ULL;

    // ---- fused g+x projection, 64 iterations, 4 LDG.128 front-batched ----
    {
        const ulonglong2* gp = g2;
        const ulonglong2* xp = x2;
        #pragma unroll 4
        for (int k = 0; k < 64; k++) {
            ulonglong2 gv0 = gp[0], gv1 = gp[4];
            ulonglong2 xv0 = xp[0], xv1 = xp[4];
            const ulonglong2* wgr = (const ulonglong2*)(&Wc[k][0]);
            const ulonglong2* wxr = (const ulonglong2*)(&Wc[64 + k][0]);
            ulonglong2 wga = wgr[q], wgb = wgr[8 + q];
            ulonglong2 wxa = wxr[q], wxb = wxr[8 + q];
            u64 gv[4] = {gv0.x, gv0.y, gv1.x, gv1.y};
            u64 xv[4] = {xv0.x, xv0.y, xv1.x, xv1.y};
            #pragma unroll
            for (int s = 0; s < 4; s++) {
                acc[0][s] = ffma2(wga.x, gv[s], acc[0][s]);
                acc[1][s] = ffma2(wga.y, gv[s], acc[1][s]);
                acc[2][s] = ffma2(wgb.x, gv[s], acc[2][s]);
                acc[3][s] = ffma2(wgb.y, gv[s], acc[3][s]);
            }
            #pragma unroll
            for (int s = 0; s < 4; s++) {
                acc[0][s] = ffma2(wxa.x, xv[s], acc[0][s]);
                acc[1][s] = ffma2(wxa.y, xv[s], acc[1][s]);
                acc[2][s] = ffma2(wxb.x, xv[s], acc[2][s]);
                acc[3][s] = ffma2(wxb.y, xv[s], acc[3][s]);
            }
            gp += PLANE2;
            xp += PLANE2;
        }
    }

    // ---- relu + partial Wpsi dot (this lane's 4 channels, 4 streams) ----
    float sx[4] = {0.f, 0.f, 0.f, 0.f};
    float sy[4] = {0.f, 0.f, 0.f, 0.f};
    #pragma unroll
    for (int i = 0; i < 4; i++) {
        float wp = wpsi_s[4 * q + i];
        #pragma unroll
        for (int s = 0; s < 4; s++) {
            float2 a = unpack2(acc[i][s]);
            sx[s] = fmaf(fmaxf(a.x, 0.f), wp, sx[s]);
            sy[s] = fmaf(fmaxf(a.y, 0.f), wp, sy[s]);
        }
    }
    // Reduce across the 8 q-lanes sharing each pair (masks 1,2,4).
    u64 psi[4];
    #pragma unroll
    for (int s = 0; s < 4; s++) {
        sx[s] += __shfl_xor_sync(0xffffffffu, sx[s], 1);
        sx[s] += __shfl_xor_sync(0xffffffffu, sx[s], 2);
        sx[s] += __shfl_xor_sync(0xffffffffu, sx[s], 4);
        sy[s] += __shfl_xor_sync(0xffffffffu, sy[s], 1);
        sy[s] += __shfl_xor_sync(0xffffffffu, sy[s], 2);
        sy[s] += __shfl_xor_sync(0xffffffffu, sy[s], 4);
        float px = 1.f / (1.f + __expf(-sx[s]));
        float py = 1.f / (1.f + __expf(-sy[s]));
        psi[s] = pack2(px, py);
    }

    // ---- out[c] = x[c] * psi : lane q writes channels [8q, 8q+8) ----
    const ulonglong2* xe = x2 + (size_t)(8 * q) * PLANE2;
    ulonglong2*       oe = (ulonglong2*)out + cbase + (size_t)(8 * q) * PLANE2;
    #pragma unroll 2
    for (int c = 0; c < 8; c++) {
        size_t pb = (size_t)c * PLANE2;
        ulonglong2 xv0 = xe[pb], xv1 = xe[pb + 4];
        ulonglong2 o0, o1;
        o0.x = fmul2(xv0.x, psi[0]);
        o0.y = fmul2(xv0.y, psi[1]);
        o1.x = fmul2(xv1.x, psi[2]);
        o1.y = fmul2(xv1.y, psi[3]);
        oe[pb]     = o0;
        oe[pb + 4] = o1;
    }
}

extern "C" void kernel_launch(void* const* d_in, const int* in_sizes, int n_in,
                              void* d_out, int out_size)
{
    const float* x    = (const float*)d_in[0];
    const float* g    = (const float*)d_in[1];
    const float* Wg   = (const float*)d_in[2];
    const float* Wx   = (const float*)d_in[3];
    const float* Wpsi = (const float*)d_in[4];
    float* out = (float*)d_out;

    // 262144 voxel pairs / 16 pairs-per-warp = 16384 warps = 2048 blocks
    attn_gate_kernel<<<2048, 256>>>(x, g, Wg, Wx, Wpsi, out);
}

// round 13
// speedup vs baseline: 1.4006x; 1.4006x over previous
#include <cuda_runtime.h>
#include <cuda_bf16.h>

// AttentionGate fused kernel, round 11: R9 tile + software pipelining.
//
// psi = sigmoid(Wpsi . relu(Wg@g + Wx@x));  out = x * psi
// B=2, CF=CG=64, CI=32, DHW=64^3=262144.
//
// Evidence: runtime tracks L1tex wavefront count across rounds; R9 (8 streams,
// 2 LDS.128/k) had the minimum but was DRAM-latency exposed (issue 20.8%,
// occ 22%, nothing >59%). This round keeps R9's instruction counts and adds
// a 2-deep double-buffered pipeline so activation LDG.128s are issued a full
// iteration before consumption (~8 in flight/warp), plus __ldcs on g
// (read-once) and __stcs on out to keep x L2-resident for the epilogue.

#define HALFV  131072           // u64 (f32x2) elements per channel-plane
#define PLANE2 65536            // ulonglong2 elements per channel-plane

typedef unsigned long long u64;

__device__ __forceinline__ u64 ffma2(u64 a, u64 b, u64 c) {
    u64 d;
    asm("fma.rn.f32x2 %0, %1, %2, %3;" : "=l"(d) : "l"(a), "l"(b), "l"(c));
    return d;
}
__device__ __forceinline__ u64 fmul2(u64 a, u64 b) {
    u64 d;
    asm("mul.rn.f32x2 %0, %1, %2;" : "=l"(d) : "l"(a), "l"(b));
    return d;
}
__device__ __forceinline__ u64 pack2(float lo, float hi) {
    u64 r;
    asm("mov.b64 %0, {%1, %2};" : "=l"(r) : "f"(lo), "f"(hi));
    return r;
}
__device__ __forceinline__ float2 unpack2(u64 v) {
    float2 r;
    asm("mov.b64 {%0, %1}, %2;" : "=f"(r.x), "=f"(r.y) : "l"(v));
    return r;
}

__global__ __launch_bounds__(256, 2)
void attn_gate_kernel(const float* __restrict__ x,
                      const float* __restrict__ g,
                      const float* __restrict__ Wg,
                      const float* __restrict__ Wx,
                      const float* __restrict__ Wpsi,
                      float* __restrict__ out)
{
    // Wc[k] row (32 u64): channel o = 4q + 2c + lh at u64 index 2*(8c+q)+lh;
    // warp LDS.128 #c covers chunks [8c..8c+7] -> conflict-free per phase.
    __shared__ u64   Wc[128][32];      // 32 KiB
    __shared__ float wpsi_s[32];

    for (int idx = threadIdx.x; idx < 128 * 32; idx += 256) {
        int k = idx >> 5;
        int o = idx & 31;
        int qq = o >> 2, cc = (o >> 1) & 1, lh = o & 1;
        float w = (k < 64) ? Wg[o * 64 + k] : Wx[o * 64 + (k - 64)];
        Wc[k][2 * (8 * cc + qq) + lh] = pack2(w, w);
    }
    if (threadIdx.x < 32) wpsi_s[threadIdx.x] = Wpsi[threadIdx.x];
    __syncthreads();

    int t    = blockIdx.x * 256 + threadIdx.x;
    int lane = t & 31;
    int wid  = t >> 5;            // 0..8191
    int gl   = lane >> 3;         // 0..3 spatial subgroup
    int q    = lane & 7;          // CI eighth: channels [4q, 4q+4)

    int pbase = wid * 32;                        // warp's first voxel pair
    int b     = pbase >> 17;                     // batch
    int sp    = (pbase & (HALFV - 1)) + gl * 2;  // first pair (even)

    size_t cbase = (size_t)(b * 64) * PLANE2 + (sp >> 1);
    const ulonglong2* g2 = (const ulonglong2*)g + cbase;
    const ulonglong2* x2 = (const ulonglong2*)x + cbase;

    u64 acc[4][8];                // [channel-in-eighth][stream u64]
    #pragma unroll
    for (int i = 0; i < 4; i++)
        #pragma unroll
        for (int s = 0; s < 8; s++) acc[i][s] = 0ULL;

    // Per-k compute: 8 streams from 4 ulonglong2, weights row wr (2 LDS.128).
#define AG_COMPUTE(V0, V1, V2, V3, WROW)                                   \
    {                                                                      \
        const ulonglong2* wrp = (const ulonglong2*)(WROW);                 \
        ulonglong2 wa = wrp[q];                                            \
        ulonglong2 wb = wrp[8 + q];                                        \
        u64 v[8] = {V0.x, V0.y, V1.x, V1.y, V2.x, V2.y, V3.x, V3.y};      \
        _Pragma("unroll")                                                  \
        for (int s = 0; s < 8; s++) {                                      \
            acc[0][s] = ffma2(wa.x, v[s], acc[0][s]);                      \
            acc[1][s] = ffma2(wa.y, v[s], acc[1][s]);                      \
            acc[2][s] = ffma2(wb.x, v[s], acc[2][s]);                      \
            acc[3][s] = ffma2(wb.y, v[s], acc[3][s]);                      \
        }                                                                  \
    }

    // ---- g projection, double-buffered (g is read-once: __ldcs) ----
    {
        const ulonglong2* p = g2;
        ulonglong2 A0, A1, A2, A3, B0, B1, B2, B3;
        A0 = __ldcs(p);  A1 = __ldcs(p + 4);
        A2 = __ldcs(p + 8); A3 = __ldcs(p + 12); p += PLANE2;
        B0 = __ldcs(p);  B1 = __ldcs(p + 4);
        B2 = __ldcs(p + 8); B3 = __ldcs(p + 12); p += PLANE2;
        #pragma unroll 1
        for (int kk = 0; kk < 62; kk += 2) {
            AG_COMPUTE(A0, A1, A2, A3, &Wc[kk][0]);
            A0 = __ldcs(p);  A1 = __ldcs(p + 4);
            A2 = __ldcs(p + 8); A3 = __ldcs(p + 12); p += PLANE2;
            AG_COMPUTE(B0, B1, B2, B3, &Wc[kk + 1][0]);
            B0 = __ldcs(p);  B1 = __ldcs(p + 4);
            B2 = __ldcs(p + 8); B3 = __ldcs(p + 12); p += PLANE2;
        }
        AG_COMPUTE(A0, A1, A2, A3, &Wc[62][0]);
        AG_COMPUTE(B0, B1, B2, B3, &Wc[63][0]);
    }

    // ---- x projection, double-buffered (default policy: keep in L2) ----
    {
        const ulonglong2* p = x2;
        ulonglong2 A0, A1, A2, A3, B0, B1, B2, B3;
        A0 = p[0];  A1 = p[4];  A2 = p[8];  A3 = p[12];  p += PLANE2;
        B0 = p[0];  B1 = p[4];  B2 = p[8];  B3 = p[12];  p += PLANE2;
        #pragma unroll 1
        for (int kk = 0; kk < 62; kk += 2) {
            AG_COMPUTE(A0, A1, A2, A3, &Wc[64 + kk][0]);
            A0 = p[0];  A1 = p[4];  A2 = p[8];  A3 = p[12];  p += PLANE2;
            AG_COMPUTE(B0, B1, B2, B3, &Wc[64 + kk + 1][0]);
            B0 = p[0];  B1 = p[4];  B2 = p[8];  B3 = p[12];  p += PLANE2;
        }
        AG_COMPUTE(A0, A1, A2, A3, &Wc[126][0]);
        AG_COMPUTE(B0, B1, B2, B3, &Wc[127][0]);
    }
#undef AG_COMPUTE

    // ---- relu + partial Wpsi dot (this lane's 4 channels, 8 streams) ----
    float sx[8], sy[8];
    #pragma unroll
    for (int s = 0; s < 8; s++) { sx[s] = 0.f; sy[s] = 0.f; }
    #pragma unroll
    for (int i = 0; i < 4; i++) {
        float wp = wpsi_s[4 * q + i];
        #pragma unroll
        for (int s = 0; s < 8; s++) {
            float2 a = unpack2(acc[i][s]);
            sx[s] = fmaf(fmaxf(a.x, 0.f), wp, sx[s]);
            sy[s] = fmaf(fmaxf(a.y, 0.f), wp, sy[s]);
        }
    }
    // Reduce across the 8 q-lanes sharing each pair (masks 1,2,4).
    u64 psiA[4], psiB[4];
    #pragma unroll
    for (int s = 0; s < 8; s++) {
        sx[s] += __shfl_xor_sync(0xffffffffu, sx[s], 1);
        sx[s] += __shfl_xor_sync(0xffffffffu, sx[s], 2);
        sx[s] += __shfl_xor_sync(0xffffffffu, sx[s], 4);
        sy[s] += __shfl_xor_sync(0xffffffffu, sy[s], 1);
        sy[s] += __shfl_xor_sync(0xffffffffu, sy[s], 2);
        sy[s] += __shfl_xor_sync(0xffffffffu, sy[s], 4);
        float px = 1.f / (1.f + __expf(-sx[s]));
        float py = 1.f / (1.f + __expf(-sy[s]));
        u64 p = pack2(px, py);
        if (s & 1) psiB[s >> 1] = p; else psiA[s >> 1] = p;
    }

    // ---- out[c] = x[c] * psi : lane q writes channels [8q, 8q+8) ----
    const ulonglong2* xe = x2 + (size_t)(8 * q) * PLANE2;
    ulonglong2*       oe = (ulonglong2*)out + cbase + (size_t)(8 * q) * PLANE2;
    #pragma unroll 2
    for (int c = 0; c < 8; c++) {
        size_t pb = (size_t)c * PLANE2;
        #pragma unroll
        for (int j = 0; j < 4; j++) {
            ulonglong2 xv = xe[pb + 4 * j];
            ulonglong2 ov;
            ov.x = fmul2(xv.x, psiA[j]);
            ov.y = fmul2(xv.y, psiB[j]);
            __stcs(&oe[pb + 4 * j], ov);
        }
    }
}

extern "C" void kernel_launch(void* const* d_in, const int* in_sizes, int n_in,
                              void* d_out, int out_size)
{
    const float* x    = (const float*)d_in[0];
    const float* g    = (const float*)d_in[1];
    const float* Wg   = (const float*)d_in[2];
    const float* Wx   = (const float*)d_in[3];
    const float* Wpsi = (const float*)d_in[4];
    float* out = (float*)d_out;

    // 262144 voxel pairs / 32 pairs-per-warp = 8192 warps = 1024 blocks
    attn_gate_kernel<<<1024, 256>>>(x, g, Wg, Wx, Wpsi, out);
}

// round 16
// speedup vs baseline: 1.7105x; 1.2213x over previous
#include <cuda_runtime.h>
#include <cuda_bf16.h>

// AttentionGate fused kernel, round 14: cp.async SMEM staging.
//
// psi = sigmoid(Wpsi . relu(Wg@g + Wx@x));  out = x * psi
// B=2, CF=CG=64, CI=32, DHW=64^3=262144.
//
// Unified model from R3-R13: every variant is DRAM-bound at ~1.4TB/s because
// q-duplicated LDG addresses leave only ~64B unique per load instruction ->
// ~4-8KB in flight per SM (< the ~19KB Little's-law need). Fix: decouple DRAM
// from registers with cp.async (LDGSTS, zero register cost) into triple-
// buffered SMEM chunks (8 ch x 512 pairs = 32KB each); compute (R9-proven
// math) reads from SMEM broadcast. FFMA2 pipe (~60us) becomes the floor.

#define HALFV  131072           // u64 (f32x2) elements per channel-plane
#define PLANE2 65536            // ulonglong2 elements per channel-plane

typedef unsigned long long u64;

__device__ __forceinline__ u64 ffma2(u64 a, u64 b, u64 c) {
    u64 d;
    asm("fma.rn.f32x2 %0, %1, %2, %3;" : "=l"(d) : "l"(a), "l"(b), "l"(c));
    return d;
}
__device__ __forceinline__ u64 fmul2(u64 a, u64 b) {
    u64 d;
    asm("mul.rn.f32x2 %0, %1, %2;" : "=l"(d) : "l"(a), "l"(b));
    return d;
}
__device__ __forceinline__ u64 pack2(float lo, float hi) {
    u64 r;
    asm("mov.b64 %0, {%1, %2};" : "=l"(r) : "f"(lo), "f"(hi));
    return r;
}
__device__ __forceinline__ float2 unpack2(u64 v) {
    float2 r;
    asm("mov.b64 {%0, %1}, %2;" : "=f"(r.x), "=f"(r.y) : "l"(v));
    return r;
}
__device__ __forceinline__ void cpasync16(void* sdst, const void* gsrc) {
    unsigned sa = (unsigned)__cvta_generic_to_shared(sdst);
    asm volatile("cp.async.cg.shared.global [%0], [%1], 16;"
                 :: "r"(sa), "l"(gsrc) : "memory");
}
#define CP_COMMIT() asm volatile("cp.async.commit_group;" ::: "memory")
#define CP_WAIT(N)  asm volatile("cp.async.wait_group %0;" :: "n"(N) : "memory")

// Dynamic SMEM layout (u64 units):
//   [0, 4096)            Wc[128][32]  (packed (w,w) pairs, R9 layout)
//   [4096, 4112)         wpsi (32 floats)
//   [4112, 4112+3*4096)  Abuf[3][8 ch][512 pairs]
#define WC_OFF   0
#define WPSI_OFF 4096
#define AB_OFF   4112
#define SMEM_U64 (4112 + 3 * 4096)           // 16400 u64 = 131200 B

__global__ __launch_bounds__(512, 1)
void attn_gate_kernel(const float* __restrict__ x,
                      const float* __restrict__ g,
                      const float* __restrict__ Wg,
                      const float* __restrict__ Wx,
                      const float* __restrict__ Wpsi,
                      float* __restrict__ out)
{
    extern __shared__ u64 smem[];
    u64*   Wc     = smem + WC_OFF;
    float* wpsi_s = (float*)(smem + WPSI_OFF);
    u64*   Abuf   = smem + AB_OFF;

    int tid = threadIdx.x;

    // ---- weights into SMEM: channel o = 4q + 2c + lh at u64 idx 2*(8c+q)+lh
    for (int idx = tid; idx < 128 * 32; idx += 512) {
        int k = idx >> 5;
        int o = idx & 31;
        int qq = o >> 2, cc = (o >> 1) & 1, lh = o & 1;
        float w = (k < 64) ? Wg[o * 64 + k] : Wx[o * 64 + (k - 64)];
        Wc[(size_t)k * 32 + 2 * (8 * cc + qq) + lh] = pack2(w, w);
    }
    if (tid < 32) wpsi_s[tid] = Wpsi[tid];
    // (ordered before compute by the per-chunk __syncthreads below)

    int q  = tid & 7;             // CI eighth: channels [4q, 4q+4)
    int o  = tid >> 3;            // pair-owner 0..63 (8 pairs each)
    int o4 = o * 4;               // owner's first ulonglong2 in a ch row

    int pbase = blockIdx.x * 512;            // CTA's first voxel pair
    int b64   = (pbase >> 17) * 64;          // batch * 64 channels
    int cu2   = (pbase & (HALFV - 1)) >> 1;  // u2 index within plane

    const ulonglong2* gB = (const ulonglong2*)g;
    const ulonglong2* xB = (const ulonglong2*)x;

    // chunk c: tensor (c<8 ? g : x), channels k0 = (c&7)*8 .. +8
#define LOAD_CHUNK(C, BUF)                                                  \
    {                                                                       \
        const ulonglong2* sb = ((C) < 8) ? gB : xB;                         \
        int k0 = ((C) & 7) * 8;                                             \
        _Pragma("unroll")                                                   \
        for (int j = 0; j < 4; j++) {                                       \
            int idx  = tid + 512 * j;                                       \
            int ich  = idx >> 8;                                            \
            int pos2 = idx & 255;                                           \
            const ulonglong2* gp =                                          \
                sb + (size_t)(b64 + k0 + ich) * PLANE2 + cu2 + pos2;        \
            cpasync16(Abuf + (size_t)(BUF) * 4096 + ich * 512 + pos2 * 2,   \
                      gp);                                                  \
        }                                                                   \
    }

    u64 acc[4][8];
    #pragma unroll
    for (int i = 0; i < 4; i++)
        #pragma unroll
        for (int s = 0; s < 8; s++) acc[i][s] = 0ULL;

    LOAD_CHUNK(0, 0); CP_COMMIT();
    LOAD_CHUNK(1, 1); CP_COMMIT();

    #pragma unroll 1
    for (int c = 0; c < 16; c++) {
        int nb = (c + 2) % 3;
        if (c + 2 < 16) {
            LOAD_CHUNK(c + 2, nb); CP_COMMIT();
        }
        if      (c < 14)  CP_WAIT(2);
        else if (c == 14) CP_WAIT(1);
        else              CP_WAIT(0);
        __syncthreads();

        const u64* buf = Abuf + (size_t)(c % 3) * 4096;
        #pragma unroll
        for (int i = 0; i < 8; i++) {
            int k = c * 8 + i;
            const ulonglong2* wrp = (const ulonglong2*)(Wc + (size_t)k * 32);
            ulonglong2 wa = wrp[q];
            ulonglong2 wb = wrp[8 + q];
            const ulonglong2* ap = (const ulonglong2*)(buf + i * 512) + o4;
            ulonglong2 a0 = ap[0], a1 = ap[1], a2 = ap[2], a3 = ap[3];
            u64 v[8] = {a0.x, a0.y, a1.x, a1.y, a2.x, a2.y, a3.x, a3.y};
            #pragma unroll
            for (int s = 0; s < 8; s++) {
                acc[0][s] = ffma2(wa.x, v[s], acc[0][s]);
                acc[1][s] = ffma2(wa.y, v[s], acc[1][s]);
                acc[2][s] = ffma2(wb.x, v[s], acc[2][s]);
                acc[3][s] = ffma2(wb.y, v[s], acc[3][s]);
            }
        }
        __syncthreads();   // buf (c%3) free before iter c+1 loads chunk c+3
    }
#undef LOAD_CHUNK

    // ---- relu + partial Wpsi dot (lane's 4 channels, 8 streams) ----
    float sx[8], sy[8];
    #pragma unroll
    for (int s = 0; s < 8; s++) { sx[s] = 0.f; sy[s] = 0.f; }
    #pragma unroll
    for (int i = 0; i < 4; i++) {
        float wp = wpsi_s[4 * q + i];
        #pragma unroll
        for (int s = 0; s < 8; s++) {
            float2 a = unpack2(acc[i][s]);
            sx[s] = fmaf(fmaxf(a.x, 0.f), wp, sx[s]);
            sy[s] = fmaf(fmaxf(a.y, 0.f), wp, sy[s]);
        }
    }
    // Reduce over the 8 q-lanes (tids o*8..o*8+7 are warp-contiguous).
    u64 psiA[4], psiB[4];
    #pragma unroll
    for (int s = 0; s < 8; s++) {
        sx[s] += __shfl_xor_sync(0xffffffffu, sx[s], 1);
        sx[s] += __shfl_xor_sync(0xffffffffu, sx[s], 2);
        sx[s] += __shfl_xor_sync(0xffffffffu, sx[s], 4);
        sy[s] += __shfl_xor_sync(0xffffffffu, sy[s], 1);
        sy[s] += __shfl_xor_sync(0xffffffffu, sy[s], 2);
        sy[s] += __shfl_xor_sync(0xffffffffu, sy[s], 4);
        float px = 1.f / (1.f + __expf(-sx[s]));
        float py = 1.f / (1.f + __expf(-sy[s]));
        u64 p = pack2(px, py);
        if (s & 1) psiB[s >> 1] = p; else psiA[s >> 1] = p;
    }

    // ---- out[ch] = x[ch] * psi : lane q writes channels [8q, 8q+8)
    //      for its 8 pairs (4 u2). Warp-instr addresses all distinct: 512B.
    const ulonglong2* xe = xB + (size_t)(b64 + 8 * q) * PLANE2 + cu2 + o4;
    ulonglong2*       oe = (ulonglong2*)out
                         + (size_t)(b64 + 8 * q) * PLANE2 + cu2 + o4;
    #pragma unroll 2
    for (int cch = 0; cch < 8; cch++) {
        #pragma unroll
        for (int j = 0; j < 4; j++) {
            ulonglong2 xv = xe[j];
            ulonglong2 ov;
            ov.x = fmul2(xv.x, psiA[j]);
            ov.y = fmul2(xv.y, psiB[j]);
            __stcs(&oe[j], ov);
        }
        xe += PLANE2;
        oe += PLANE2;
    }
}

extern "C" void kernel_launch(void* const* d_in, const int* in_sizes, int n_in,
                              void* d_out, int out_size)
{
    const float* x    = (const float*)d_in[0];
    const float* g    = (const float*)d_in[1];
    const float* Wg   = (const float*)d_in[2];
    const float* Wx   = (const float*)d_in[3];
    const float* Wpsi = (const float*)d_in[4];
    float* out = (float*)d_out;

    static int smem_set = 0;
    if (!smem_set) {
        cudaFuncSetAttribute(attn_gate_kernel,
                             cudaFuncAttributeMaxDynamicSharedMemorySize,
                             SMEM_U64 * 8);
        smem_set = 1;
    }
    // 262144 pairs / 512 pairs-per-CTA = 512 blocks of 512 threads
    attn_gate_kernel<<<512, 512, SMEM_U64 * 8>>>(x, g, Wg, Wx, Wpsi, out);
}

// round 17
// speedup vs baseline: 2.0068x; 1.1733x over previous
#include <cuda_runtime.h>
#include <cuda_bf16.h>

// AttentionGate fused kernel, round 17: two independent pipelines per SM.
//
// psi = sigmoid(Wpsi . relu(Wg@g + Wx@x));  out = x * psi
// B=2, CF=CG=64, CI=32, DHW=64^3=262144.
//
// R16 (1 CTA x 512 thr, 3-buf depth-2) hit 215us with DRAM still at 21%:
// the whole CTA convoys on one CP_WAIT/__syncthreads pipeline, capping
// in-flight bytes. This round: 2 CTAs x 256 threads per SM, each with its
// own 4-buffer depth-3 cp.async pipeline over 16KB chunks (8 ch x 256
// pairs). Per-thread math identical to R16 (proven). 2 desynchronized
// pipelines -> ~2x effective MLP + barrier-stall overlap.

#define HALFV  131072           // u64 (f32x2) elements per channel-plane
#define PLANE2 65536            // ulonglong2 elements per channel-plane

typedef unsigned long long u64;

__device__ __forceinline__ u64 ffma2(u64 a, u64 b, u64 c) {
    u64 d;
    asm("fma.rn.f32x2 %0, %1, %2, %3;" : "=l"(d) : "l"(a), "l"(b), "l"(c));
    return d;
}
__device__ __forceinline__ u64 fmul2(u64 a, u64 b) {
    u64 d;
    asm("mul.rn.f32x2 %0, %1, %2;" : "=l"(d) : "l"(a), "l"(b));
    return d;
}
__device__ __forceinline__ u64 pack2(float lo, float hi) {
    u64 r;
    asm("mov.b64 %0, {%1, %2};" : "=l"(r) : "f"(lo), "f"(hi));
    return r;
}
__device__ __forceinline__ float2 unpack2(u64 v) {
    float2 r;
    asm("mov.b64 {%0, %1}, %2;" : "=f"(r.x), "=f"(r.y) : "l"(v));
    return r;
}
__device__ __forceinline__ void cpasync16(void* sdst, const void* gsrc) {
    unsigned sa = (unsigned)__cvta_generic_to_shared(sdst);
    asm volatile("cp.async.cg.shared.global [%0], [%1], 16;"
                 :: "r"(sa), "l"(gsrc) : "memory");
}
#define CP_COMMIT() asm volatile("cp.async.commit_group;" ::: "memory")
#define CP_WAIT(N)  asm volatile("cp.async.wait_group %0;" :: "n"(N) : "memory")

// Dynamic SMEM layout (u64 units), per CTA:
//   [0, 4096)            Wc[128][32]  (packed (w,w) pairs, R9 layout)
//   [4096, 4112)         wpsi (32 floats)
//   [4112, 4112+4*2048)  Abuf[4][8 ch][256 pairs]   (4 x 16KB)
#define WC_OFF   0
#define WPSI_OFF 4096
#define AB_OFF   4112
#define SMEM_U64 (4112 + 4 * 2048)           // 12304 u64 = 98432 B

__global__ __launch_bounds__(256, 2)
void attn_gate_kernel(const float* __restrict__ x,
                      const float* __restrict__ g,
                      const float* __restrict__ Wg,
                      const float* __restrict__ Wx,
                      const float* __restrict__ Wpsi,
                      float* __restrict__ out)
{
    extern __shared__ u64 smem[];
    u64*   Wc     = smem + WC_OFF;
    float* wpsi_s = (float*)(smem + WPSI_OFF);
    u64*   Abuf   = smem + AB_OFF;

    int tid = threadIdx.x;

    // ---- weights into SMEM: channel o = 4q + 2c + lh at u64 idx 2*(8c+q)+lh
    for (int idx = tid; idx < 128 * 32; idx += 256) {
        int k = idx >> 5;
        int o = idx & 31;
        int qq = o >> 2, cc = (o >> 1) & 1, lh = o & 1;
        float w = (k < 64) ? Wg[o * 64 + k] : Wx[o * 64 + (k - 64)];
        Wc[(size_t)k * 32 + 2 * (8 * cc + qq) + lh] = pack2(w, w);
    }
    if (tid < 32) wpsi_s[tid] = Wpsi[tid];
    // (ordered before compute by the per-chunk __syncthreads below)

    int q  = tid & 7;             // CI eighth: channels [4q, 4q+4)
    int o  = tid >> 3;            // pair-owner 0..31 (8 pairs each)
    int o4 = o * 4;               // owner's first ulonglong2 in a ch row

    int pbase = blockIdx.x * 256;            // CTA's first voxel pair
    int b64   = (pbase >> 17) * 64;          // batch * 64 channels
    int cu2   = (pbase & (HALFV - 1)) >> 1;  // u2 index within plane

    const ulonglong2* gB = (const ulonglong2*)g;
    const ulonglong2* xB = (const ulonglong2*)x;

    // chunk c: tensor (c<8 ? g : x), channels k0 = (c&7)*8 .. +8
    // 8 ch x 128 u2 = 1024 cp.async of 16B = 4 per thread.
#define LOAD_CHUNK(C, BUF)                                                  \
    {                                                                       \
        const ulonglong2* sb = ((C) < 8) ? gB : xB;                         \
        int k0 = ((C) & 7) * 8;                                             \
        _Pragma("unroll")                                                   \
        for (int j = 0; j < 4; j++) {                                       \
            int idx  = tid + 256 * j;                                       \
            int ich  = idx >> 7;                                            \
            int pos2 = idx & 127;                                           \
            const ulonglong2* gp =                                          \
                sb + (size_t)(b64 + k0 + ich) * PLANE2 + cu2 + pos2;        \
            cpasync16(Abuf + (size_t)(BUF) * 2048 + ich * 256 + pos2 * 2,   \
                      gp);                                                  \
        }                                                                   \
    }

    u64 acc[4][8];
    #pragma unroll
    for (int i = 0; i < 4; i++)
        #pragma unroll
        for (int s = 0; s < 8; s++) acc[i][s] = 0ULL;

    LOAD_CHUNK(0, 0); CP_COMMIT();
    LOAD_CHUNK(1, 1); CP_COMMIT();
    LOAD_CHUNK(2, 2); CP_COMMIT();

    #pragma unroll 1
    for (int c = 0; c < 16; c++) {
        if (c + 3 < 16) {
            LOAD_CHUNK(c + 3, (c + 3) & 3); CP_COMMIT();
        }
        if      (c < 13)  CP_WAIT(3);
        else if (c == 13) CP_WAIT(2);
        else if (c == 14) CP_WAIT(1);
        else              CP_WAIT(0);
        __syncthreads();

        const u64* buf = Abuf + (size_t)(c & 3) * 2048;
        #pragma unroll
        for (int i = 0; i < 8; i++) {
            int k = c * 8 + i;
            const ulonglong2* wrp = (const ulonglong2*)(Wc + (size_t)k * 32);
            ulonglong2 wa = wrp[q];
            ulonglong2 wb = wrp[8 + q];
            const ulonglong2* ap = (const ulonglong2*)(buf + i * 256) + o4;
            ulonglong2 a0 = ap[0], a1 = ap[1], a2 = ap[2], a3 = ap[3];
            u64 v[8] = {a0.x, a0.y, a1.x, a1.y, a2.x, a2.y, a3.x, a3.y};
            #pragma unroll
            for (int s = 0; s < 8; s++) {
                acc[0][s] = ffma2(wa.x, v[s], acc[0][s]);
                acc[1][s] = ffma2(wa.y, v[s], acc[1][s]);
                acc[2][s] = ffma2(wb.x, v[s], acc[2][s]);
                acc[3][s] = ffma2(wb.y, v[s], acc[3][s]);
            }
        }
        __syncthreads();   // all warps done with buf (c&3) before overwrite
    }
#undef LOAD_CHUNK

    // ---- relu + partial Wpsi dot (lane's 4 channels, 8 streams) ----
    float sx[8], sy[8];
    #pragma unroll
    for (int s = 0; s < 8; s++) { sx[s] = 0.f; sy[s] = 0.f; }
    #pragma unroll
    for (int i = 0; i < 4; i++) {
        float wp = wpsi_s[4 * q + i];
        #pragma unroll
        for (int s = 0; s < 8; s++) {
            float2 a = unpack2(acc[i][s]);
            sx[s] = fmaf(fmaxf(a.x, 0.f), wp, sx[s]);
            sy[s] = fmaf(fmaxf(a.y, 0.f), wp, sy[s]);
        }
    }
    // Reduce over the 8 q-lanes (tids o*8..o*8+7 are warp-contiguous).
    u64 psiA[4], psiB[4];
    #pragma unroll
    for (int s = 0; s < 8; s++) {
        sx[s] += __shfl_xor_sync(0xffffffffu, sx[s], 1);
        sx[s] += __shfl_xor_sync(0xffffffffu, sx[s], 2);
        sx[s] += __shfl_xor_sync(0xffffffffu, sx[s], 4);
        sy[s] += __shfl_xor_sync(0xffffffffu, sy[s], 1);
        sy[s] += __shfl_xor_sync(0xffffffffu, sy[s], 2);
        sy[s] += __shfl_xor_sync(0xffffffffu, sy[s], 4);
        float px = 1.f / (1.f + __expf(-sx[s]));
        float py = 1.f / (1.f + __expf(-sy[s]));
        u64 p = pack2(px, py);
        if (s & 1) psiB[s >> 1] = p; else psiA[s >> 1] = p;
    }

    // ---- out[ch] = x[ch] * psi : lane q writes channels [8q, 8q+8)
    const ulonglong2* xe = xB + (size_t)(b64 + 8 * q) * PLANE2 + cu2 + o4;
    ulonglong2*       oe = (ulonglong2*)out
                         + (size_t)(b64 + 8 * q) * PLANE2 + cu2 + o4;
    #pragma unroll 2
    for (int cch = 0; cch < 8; cch++) {
        #pragma unroll
        for (int j = 0; j < 4; j++) {
            ulonglong2 xv = xe[j];
            ulonglong2 ov;
            ov.x = fmul2(xv.x, psiA[j]);
            ov.y = fmul2(xv.y, psiB[j]);
            __stcs(&oe[j], ov);
        }
        xe += PLANE2;
        oe += PLANE2;
    }
}

extern "C" void kernel_launch(void* const* d_in, const int* in_sizes, int n_in,
                              void* d_out, int out_size)
{
    const float* x    = (const float*)d_in[0];
    const float* g    = (const float*)d_in[1];
    const float* Wg   = (const float*)d_in[2];
    const float* Wx   = (const float*)d_in[3];
    const float* Wpsi = (const float*)d_in[4];
    float* out = (float*)d_out;

    static int smem_set = 0;
    if (!smem_set) {
        cudaFuncSetAttribute(attn_gate_kernel,
                             cudaFuncAttributeMaxDynamicSharedMemorySize,
                             SMEM_U64 * 8);
        smem_set = 1;
    }
    // 262144 pairs / 256 pairs-per-CTA = 1024 blocks of 256 threads, 2/SM
    attn_gate_kernel<<<1024, 256, SMEM_U64 * 8>>>(x, g, Wg, Wx, Wpsi, out);
}